// round 1
// baseline (speedup 1.0000x reference)
#include <cuda_runtime.h>
#include <math.h>

#define BATCH 8
#define SEQ   4096
#define DIM   64
#define TQ    64
#define TK    64
#define KSTR  68   // Ks row stride (floats) — breaks bank conflicts on strided col reads

// Fused flash-style self-attention: Y = softmax(X X^T) X, per batch.
// Grid: (SEQ/TQ, BATCH). Block: 256 threads as 16x16 (ty=rows, tx=cols),
// each thread owns a 4x4 micro-tile. Online softmax; P bounced via SMEM.
__global__ __launch_bounds__(256, 2)
void attn_fused_kernel(const float* __restrict__ X, float* __restrict__ Y) {
    extern __shared__ float sm[];
    float* Qs = sm;                        // TQ x DIM   (stride 64)
    float* Ks = Qs + TQ * DIM;             // TK x KSTR  (stride 68)
    float* Ps = Ks + TK * KSTR;            // TQ x DIM   (stride 64)

    const int b   = blockIdx.y;
    const int q0  = blockIdx.x * TQ;
    const int tid = threadIdx.x;
    const int tx  = tid & 15;
    const int ty  = tid >> 4;

    const float* Xb = X + (size_t)b * SEQ * DIM;

    // ---- Load Q tile (coalesced, float4) ----
    #pragma unroll
    for (int t = 0; t < 4; t++) {
        int e   = tid + t * 256;       // float4 index within 64x64 tile
        int row = e >> 4;              // 16 float4 per row
        int c4  = (e & 15) << 2;
        float4 v = *(const float4*)&Xb[(q0 + row) * DIM + c4];
        *(float4*)&Qs[row * DIM + c4] = v;
    }

    float m[4], l[4], o[4][4];
    #pragma unroll
    for (int i = 0; i < 4; i++) {
        m[i] = -INFINITY; l[i] = 0.f;
        #pragma unroll
        for (int j = 0; j < 4; j++) o[i][j] = 0.f;
    }

    for (int kt = 0; kt < SEQ; kt += TK) {
        __syncthreads();   // previous O-GEMM done reading Ks/Ps

        // ---- Load K tile (= V tile) ----
        #pragma unroll
        for (int t = 0; t < 4; t++) {
            int e   = tid + t * 256;
            int row = e >> 4;
            int c4  = (e & 15) << 2;
            float4 v = *(const float4*)&Xb[(kt + row) * DIM + c4];
            *(float4*)&Ks[row * KSTR + c4] = v;
        }
        __syncthreads();

        // ---- S = Q K^T : rows r = ty*4+i, cols c = tx + 16*j ----
        float s[4][4];
        #pragma unroll
        for (int i = 0; i < 4; i++)
            #pragma unroll
            for (int j = 0; j < 4; j++) s[i][j] = 0.f;

        #pragma unroll
        for (int d4 = 0; d4 < DIM; d4 += 4) {
            float4 qv[4], kv[4];
            #pragma unroll
            for (int i = 0; i < 4; i++)
                qv[i] = *(const float4*)&Qs[(ty * 4 + i) * DIM + d4];   // broadcast
            #pragma unroll
            for (int j = 0; j < 4; j++)
                kv[j] = *(const float4*)&Ks[(tx + 16 * j) * KSTR + d4]; // 2-way max
            #pragma unroll
            for (int i = 0; i < 4; i++)
                #pragma unroll
                for (int j = 0; j < 4; j++)
                    s[i][j] += qv[i].x * kv[j].x + qv[i].y * kv[j].y +
                               qv[i].z * kv[j].z + qv[i].w * kv[j].w;
        }

        // ---- Online softmax per row (reduce across tx, width-16 shuffles) ----
        #pragma unroll
        for (int i = 0; i < 4; i++) {
            float mt = fmaxf(fmaxf(s[i][0], s[i][1]), fmaxf(s[i][2], s[i][3]));
            #pragma unroll
            for (int off = 8; off; off >>= 1)
                mt = fmaxf(mt, __shfl_xor_sync(0xffffffffu, mt, off, 16));
            float mn    = fmaxf(m[i], mt);
            float scale = __expf(m[i] - mn);
            float rs = 0.f;
            #pragma unroll
            for (int j = 0; j < 4; j++) { s[i][j] = __expf(s[i][j] - mn); rs += s[i][j]; }
            #pragma unroll
            for (int off = 8; off; off >>= 1)
                rs += __shfl_xor_sync(0xffffffffu, rs, off, 16);
            l[i] = l[i] * scale + rs;
            m[i] = mn;
            #pragma unroll
            for (int j = 0; j < 4; j++) o[i][j] *= scale;
            #pragma unroll
            for (int j = 0; j < 4; j++)
                Ps[(ty * 4 + i) * DIM + tx + 16 * j] = s[i][j];
        }
        __syncthreads();

        // ---- O += P * K : dcols dc = tx*4+j (contiguous float4 K reads) ----
        #pragma unroll
        for (int c4 = 0; c4 < TK; c4 += 4) {
            float4 pv[4];
            #pragma unroll
            for (int i = 0; i < 4; i++)
                pv[i] = *(const float4*)&Ps[(ty * 4 + i) * DIM + c4];   // broadcast
            #pragma unroll
            for (int cc = 0; cc < 4; cc++) {
                float4 kv = *(const float4*)&Ks[(c4 + cc) * KSTR + tx * 4]; // contiguous
                #pragma unroll
                for (int i = 0; i < 4; i++) {
                    float p = (cc == 0) ? pv[i].x : (cc == 1) ? pv[i].y
                            : (cc == 2) ? pv[i].z : pv[i].w;
                    o[i][0] += p * kv.x;
                    o[i][1] += p * kv.y;
                    o[i][2] += p * kv.z;
                    o[i][3] += p * kv.w;
                }
            }
        }
    }

    // ---- Normalize and write out (coalesced float4) ----
    #pragma unroll
    for (int i = 0; i < 4; i++) {
        float inv = 1.f / l[i];
        float4 v = make_float4(o[i][0] * inv, o[i][1] * inv,
                               o[i][2] * inv, o[i][3] * inv);
        *(float4*)&Y[((size_t)b * SEQ + q0 + ty * 4 + i) * DIM + tx * 4] = v;
    }
}

extern "C" void kernel_launch(void* const* d_in, const int* in_sizes, int n_in,
                              void* d_out, int out_size) {
    const float* X = (const float*)d_in[0];
    float* Y = (float*)d_out;

    const int smem_bytes = (TQ * DIM + TK * KSTR + TQ * DIM) * (int)sizeof(float); // 50176
    cudaFuncSetAttribute(attn_fused_kernel,
                         cudaFuncAttributeMaxDynamicSharedMemorySize, smem_bytes);

    dim3 grid(SEQ / TQ, BATCH);
    attn_fused_kernel<<<grid, 256, smem_bytes>>>(X, Y);
}